// round 14
// baseline (speedup 1.0000x reference)
#include <cuda_runtime.h>
#include <cuda_fp16.h>
#include <stdint.h>

// Problem constants
constexpr int kB  = 4;
constexpr int kH  = 8;
constexpr int kNQ = 1024;
constexpr int kNC = 8192;
constexpr int kD  = 512;
constexpr int kHD = 64;
constexpr int kSplits = 4;
constexpr int kRows = kB * kH * kNQ;   // 32768

// Q pre-scale: 1/sqrt(64) * log2(e)
constexpr float kQScale = 0.18033688011112042f;

// Scratch (allocation is forbidden; use device globals)
__device__ __align__(16) __half g_xh  [kB * kNQ * kD];        //  4 MB fp16 x
__device__ __align__(16) __half g_ctxh[kB * kNC * kD];        // 32 MB fp16 context
__device__ __align__(16) __half g_wqh [kD * kD];              // fp16 Wq
__device__ __align__(16) __half g_wkvh[kD * 2 * kD];          // fp16 Wkv
__device__ __align__(16) __half g_wouth[kD * kD];             // fp16 Wout
__device__ __align__(16) __half g_qh[kB * kH * kNQ * kHD];    //  4 MB scaled fp16 q
__device__ __align__(16) __half g_kh[kB * kH * kNC * kHD];    // 32 MB fp16 k
__device__ __align__(16) __half g_vh[kB * kH * kNC * kHD];    // 32 MB fp16 v
__device__ __align__(16) __half g_oh[kB * kNQ * kD];          //  4 MB fp16 attn out
__device__ __align__(16) float  g_po[kSplits * kRows * kHD];  // 32 MB O partials
__device__ __align__(16) float  g_pl[kSplits * kRows];        // l partials

// ---------------------------------------------------------------------------
// Helpers
// ---------------------------------------------------------------------------
__device__ __forceinline__ uint32_t smem_u32(const void* p) {
    uint32_t a;
    asm("{ .reg .u64 t; cvta.to.shared.u64 t, %1; cvt.u32.u64 %0, t; }"
        : "=r"(a) : "l"(p));
    return a;
}
#define CP16(dst_u32, src_ptr) \
    asm volatile("cp.async.cg.shared.global [%0], [%1], 16;" \
                 :: "r"(dst_u32), "l"(src_ptr) : "memory")
#define CP_COMMIT() asm volatile("cp.async.commit_group;" ::: "memory")
#define CP_WAIT0()  asm volatile("cp.async.wait_group 0;" ::: "memory")

#define LDSM4(r, addr) \
    asm volatile("ldmatrix.sync.aligned.m8n8.x4.shared.b16 {%0,%1,%2,%3}, [%4];" \
                 : "=r"((r)[0]), "=r"((r)[1]), "=r"((r)[2]), "=r"((r)[3]) : "r"(addr))
#define LDSM4T(r, addr) \
    asm volatile("ldmatrix.sync.aligned.m8n8.x4.trans.shared.b16 {%0,%1,%2,%3}, [%4];" \
                 : "=r"((r)[0]), "=r"((r)[1]), "=r"((r)[2]), "=r"((r)[3]) : "r"(addr))

// m16n8k16 fp16 mma, fp32 accumulate.
__device__ __forceinline__ void mma_f16(float d[4], const uint32_t a[4],
                                        uint32_t b0, uint32_t b1)
{
    asm volatile(
        "mma.sync.aligned.m16n8k16.row.col.f32.f16.f16.f32 "
        "{%0,%1,%2,%3}, {%4,%5,%6,%7}, {%8,%9}, {%0,%1,%2,%3};"
        : "+f"(d[0]), "+f"(d[1]), "+f"(d[2]), "+f"(d[3])
        : "r"(a[0]), "r"(a[1]), "r"(a[2]), "r"(a[3]), "r"(b0), "r"(b1));
}

// m16n8k16 fp16 mma, fp16 accumulate; d points at 2 u32 (4 halves).
__device__ __forceinline__ void mma_f16acc(uint32_t* d, const uint32_t a[4],
                                           uint32_t b0, uint32_t b1)
{
    asm volatile(
        "mma.sync.aligned.m16n8k16.row.col.f16.f16.f16.f16 "
        "{%0,%1}, {%2,%3,%4,%5}, {%6,%7}, {%0,%1};"
        : "+r"(d[0]), "+r"(d[1])
        : "r"(a[0]), "r"(a[1]), "r"(a[2]), "r"(a[3]), "r"(b0), "r"(b1));
}

// 2^x on packed f16x2
__device__ __forceinline__ uint32_t ex2u(uint32_t u) {
    uint32_t r;
    asm("ex2.approx.f16x2 %0, %1;" : "=r"(r) : "r"(u));
    return r;
}
__device__ __forceinline__ uint32_t hadd2u(uint32_t a, uint32_t b) {
    uint32_t r;
    asm("add.f16x2 %0, %1, %2;" : "=r"(r) : "r"(a), "r"(b));
    return r;
}

// ---------------------------------------------------------------------------
// fp32 -> fp16 bulk converts
// ---------------------------------------------------------------------------
__device__ __forceinline__ void cvt8(const float* __restrict__ s,
                                     __half* __restrict__ d, size_t i) {
    float4 a = *(const float4*)(s + i * 8);
    float4 b = *(const float4*)(s + i * 8 + 4);
    __half2 h[4];
    h[0] = __floats2half2_rn(a.x, a.y);
    h[1] = __floats2half2_rn(a.z, a.w);
    h[2] = __floats2half2_rn(b.x, b.y);
    h[3] = __floats2half2_rn(b.z, b.w);
    *(uint4*)(d + i * 8) = *(uint4*)h;
}

__global__ __launch_bounds__(256) void cvt_f2h(
    const float* __restrict__ src, __half* __restrict__ dst, int n8)
{
    const int i = blockIdx.x * 256 + threadIdx.x;
    if (i < n8) cvt8(src, dst, (size_t)i);
}

// All three weights in one launch
__global__ __launch_bounds__(256) void cvt_weights(
    const float* __restrict__ wq, const float* __restrict__ wkv,
    const float* __restrict__ wout)
{
    const int i = blockIdx.x * 256 + threadIdx.x;   // 0..131071
    if (i < 32768) {
        cvt8(wq, g_wqh, (size_t)i);
    } else if (i < 98304) {
        cvt8(wkv, g_wkvh, (size_t)(i - 32768));
    } else {
        cvt8(wout, g_wouth, (size_t)(i - 98304));
    }
}

// ---------------------------------------------------------------------------
// Pure-fp16 tensor GEMM, CTA 128x128, 8 warps 2m x 4n, K chunks of 32,
// cp.async double-buffered staging.
// MODE 0: A=g_xh    B=g_wqh   -> g_qh (scaled fp16 scatter)
// MODE 1: A=g_ctxh  B=g_wkvh  -> g_kh/g_vh (fp16 scatter); grid n-fastest
// MODE 2: A=g_oh    B=g_wouth -> Cout fp32 (+bias)
// ---------------------------------------------------------------------------
template <int MODE>
__global__ __launch_bounds__(256) void hgemm(
    const __half* __restrict__ Ah, const __half* __restrict__ Bh,
    const float* __restrict__ bias, float* __restrict__ Cout)
{
    constexpr int N = (MODE == 1) ? 1024 : 512;
    __shared__ __align__(16) __half As[2][128 * 40];
    __shared__ __align__(16) __half Bs[2][32 * 136];

    const int tid = threadIdx.x, lane = tid & 31, wid = tid >> 5;
    const int g = lane >> 2, tq2 = (lane & 3) << 1;
    const int m0 = (MODE == 1 ? blockIdx.y : blockIdx.x) << 7;
    const int n0 = (MODE == 1 ? blockIdx.x : blockIdx.y) << 7;
    const int arow = (wid >> 2) << 6, bcol = (wid & 3) << 5;

    const uint32_t asb0 = smem_u32(As[0]), bsb0 = smem_u32(Bs[0]);
    const uint32_t asb1 = smem_u32(As[1]), bsb1 = smem_u32(Bs[1]);

    const int arow_l = (lane & 7) + ((lane >> 3) & 1) * 8;
    const int acol_l = ((lane >> 4) & 1) * 8;
    const int brow_l = (lane & 7) + ((lane >> 3) & 1) * 8;
    const int bcol_l = ((lane >> 4) & 1) * 8;

    const int ia0 = tid << 1;
    const int aR0 = ia0 >> 2,  aO0 = (ia0 & 3) << 3;
    const int aR1 = (ia0 + 1) >> 2, aO1 = ((ia0 + 1) & 3) << 3;
    const int bR0 = ia0 >> 4,  bO0 = (ia0 & 15) << 3;
    const int bR1 = (ia0 + 1) >> 4, bO1 = ((ia0 + 1) & 15) << 3;

    auto stage = [&](uint32_t ab, uint32_t bb, int k0) {
        CP16(ab + 2 * (aR0 * 40 + aO0), Ah + (size_t)(m0 + aR0) * kD + k0 + aO0);
        CP16(ab + 2 * (aR1 * 40 + aO1), Ah + (size_t)(m0 + aR1) * kD + k0 + aO1);
        CP16(bb + 2 * (bR0 * 136 + bO0), Bh + (size_t)(k0 + bR0) * N + n0 + bO0);
        CP16(bb + 2 * (bR1 * 136 + bO1), Bh + (size_t)(k0 + bR1) * N + n0 + bO1);
        CP_COMMIT();
    };

    stage(asb0, bsb0, 0);

    float acc[4][4][4] = {};

    for (int c = 0; c < 16; c++) {
        const int cur = c & 1;
        CP_WAIT0();
        __syncthreads();
        if (c < 15)
            stage(cur ? asb0 : asb1, cur ? bsb0 : bsb1, (c + 1) << 5);
        const uint32_t asb = cur ? asb1 : asb0;
        const uint32_t bsb = cur ? bsb1 : bsb0;
#pragma unroll
        for (int h16 = 0; h16 < 2; h16++) {
            uint32_t a[4][4];
#pragma unroll
            for (int mf = 0; mf < 4; mf++)
                LDSM4(a[mf], asb + 2 * ((arow + (mf << 4) + arow_l) * 40 + (h16 << 4) + acol_l));
#pragma unroll
            for (int np = 0; np < 2; np++) {
                uint32_t b[4];
                LDSM4T(b, bsb + 2 * (((h16 << 4) + brow_l) * 136 + bcol + (np << 4) + bcol_l));
#pragma unroll
                for (int mf = 0; mf < 4; mf++) {
                    mma_f16(acc[mf][2 * np + 0], a[mf], b[0], b[1]);
                    mma_f16(acc[mf][2 * np + 1], a[mf], b[2], b[3]);
                }
            }
        }
    }

    // Epilogues
#pragma unroll
    for (int mf = 0; mf < 4; mf++) {
        const int m = m0 + arow + (mf << 4) + g;
#pragma unroll
        for (int nf = 0; nf < 4; nf++) {
            const int n = n0 + bcol + (nf << 3) + tq2;
            if (MODE == 0) {
                const int b_idx = m >> 10, iq = m & 1023;
                const int h = n >> 6, d = n & 63;
                __half* p0 = g_qh + (((size_t)(b_idx * kH + h) * kNQ + iq) << 6) + d;
                *(__half2*)p0 = __floats2half2_rn(acc[mf][nf][0] * kQScale,
                                                  acc[mf][nf][1] * kQScale);
                *(__half2*)(p0 + 512) = __floats2half2_rn(acc[mf][nf][2] * kQScale,
                                                          acc[mf][nf][3] * kQScale);
            } else if (MODE == 1) {
                const int bi = m >> 13, ic = m & 8191;
                __half* dst = (n < kD) ? g_kh : g_vh;
                const int h = (n >> 6) & 7, d = n & 63;
                __half* p0 = dst + (((size_t)(bi * kH + h) * kNC + ic) << 6) + d;
                *(__half2*)p0 = __floats2half2_rn(acc[mf][nf][0], acc[mf][nf][1]);
                *(__half2*)(p0 + 512) = __floats2half2_rn(acc[mf][nf][2], acc[mf][nf][3]);
            } else {
                const float b0 = bias[n], b1 = bias[n + 1];
                *(float2*)(Cout + (size_t)m * kD + n) =
                    make_float2(acc[mf][nf][0] + b0, acc[mf][nf][1] + b1);
                *(float2*)(Cout + (size_t)(m + 8) * kD + n) =
                    make_float2(acc[mf][nf][2] + b0, acc[mf][nf][3] + b1);
            }
        }
    }
}

// ---------------------------------------------------------------------------
// Flash attention, split-KV, phase-batched, 8 warps x 16 q-rows each.
// CTA = (128-q tile, bh, split); 256 thr; kv-tile 64; double-buffered cp.async.
// Per kv tile per warp: [16 S f16acc mma] -> [ex2] -> [16 PV f32 mma].
// Low per-warp register state -> 2 CTAs/SM -> 4 warps/SMSP for latency hiding.
// ---------------------------------------------------------------------------
constexpr int H_K0 = 0;          // 64*72 halves
constexpr int H_V0 = 4608;
constexpr int H_K1 = 9216;
constexpr int H_V1 = 13824;
constexpr int AT_SMEM = 18432 * 2;   // 36864 bytes
constexpr int kTilesPerSplit = kNC / 64 / kSplits;   // 32

__global__ __launch_bounds__(256, 2) void attn_mma()
{
    extern __shared__ __align__(16) __half sh[];
    const uint32_t sb = smem_u32(sh);

    const int tid = threadIdx.x, lane = tid & 31, wid = tid >> 5;
    const int g = lane >> 2, tq2 = (lane & 3) << 1;
    const int wr = wid << 4;                    // warp's 16 q-rows
    const int bh = blockIdx.y, q0 = blockIdx.x << 7, sp = blockIdx.z;
    const int c0 = sp * kTilesPerSplit * 64;

    const __half* Qg = g_qh + ((size_t)bh * kNQ + q0) * kHD;
    const __half* Kg = g_kh + (size_t)bh * kNC * kHD + (size_t)c0 * kHD;
    const __half* Vg = g_vh + (size_t)bh * kNC * kHD + (size_t)c0 * kHD;

    const int qrow_l = (lane & 7) + ((lane >> 3) & 1) * 8;   // V rows (trans ldsm)
    const int qcol_l = ((lane >> 4) & 1) * 8;
    const int krow_l = (lane & 7) + ((lane >> 4) & 1) * 8;   // K (B) n-rows
    const int kcol_l = ((lane >> 3) & 1) * 8;

    // Stage K/V tile 0: 64 rows x 64 halves = 512 16B-segs each; 2+2 per thread
#pragma unroll
    for (int p = 0; p < 2; p++) {
        int c = (tid << 1) + p;
        int row = c >> 3, seg = (c & 7) << 3;
        CP16(sb + 2 * (H_K0 + row * 72 + seg), Kg + (row << 6) + seg);
        CP16(sb + 2 * (H_V0 + row * 72 + seg), Vg + (row << 6) + seg);
    }
    CP_COMMIT();

    // Q fragments straight from gmem (warp's 16 rows, full K=64)
    uint32_t qa[4][4];
#pragma unroll
    for (int kc = 0; kc < 4; kc++) {
        const __half* qp = Qg + (wr + g) * kHD + (kc << 4) + tq2;
        qa[kc][0] = *(const uint32_t*)qp;
        qa[kc][1] = *(const uint32_t*)(qp + 8 * kHD);
        qa[kc][2] = *(const uint32_t*)(qp + 8);
        qa[kc][3] = *(const uint32_t*)(qp + 8 * kHD + 8);
    }

    float o[8][4] = {};
    float l32[2] = {};   // rows g / g+8

    CP_WAIT0();
    __syncthreads();

    for (int tk = 0; tk < kTilesPerSplit; tk++) {
        const int cur = tk & 1;
        if (tk < kTilesPerSplit - 1) {
            const __half* Kt = Kg + (size_t)(tk + 1) * 64 * kHD;
            const __half* Vt = Vg + (size_t)(tk + 1) * 64 * kHD;
            const int kd = cur ? H_K0 : H_K1;
            const int vd = cur ? H_V0 : H_V1;
#pragma unroll
            for (int p = 0; p < 2; p++) {
                int c = (tid << 1) + p;
                int row = c >> 3, seg = (c & 7) << 3;
                CP16(sb + 2 * (kd + row * 72 + seg), Kt + (row << 6) + seg);
                CP16(sb + 2 * (vd + row * 72 + seg), Vt + (row << 6) + seg);
            }
            CP_COMMIT();
        }
        const uint32_t kbase = sb + 2 * (cur ? H_K1 : H_K0);
        const uint32_t vbase = sb + 2 * (cur ? H_V1 : H_V0);

        // ---- Phase 1: S = Q.K^T (fp16 acc), all 4 np chunks ----
        uint32_t s[4][4] = {};
#pragma unroll
        for (int np = 0; np < 4; np++) {
#pragma unroll
            for (int kc = 0; kc < 4; kc++) {
                uint32_t kb[4];
                LDSM4(kb, kbase + 2 * (((np << 4) + krow_l) * 72 + (kc << 4) + kcol_l));
                mma_f16acc(&s[np][0], qa[kc], kb[0], kb[1]);
                mma_f16acc(&s[np][2], qa[kc], kb[2], kb[3]);
            }
        }

        // ---- Phase 2: exp2 in place (A-frag order already) ----
#pragma unroll
        for (int np = 0; np < 4; np++) {
            s[np][0] = ex2u(s[np][0]);
            s[np][1] = ex2u(s[np][1]);
            s[np][2] = ex2u(s[np][2]);
            s[np][3] = ex2u(s[np][3]);
        }

        // ---- l: HADD2 trees (regs 0,2 = row g; 1,3 = row g+8) ----
        {
            uint32_t hg = hadd2u(s[0][0], s[0][2]);
            uint32_t h8 = hadd2u(s[0][1], s[0][3]);
#pragma unroll
            for (int np = 1; np < 4; np++) {
                hg = hadd2u(hg, hadd2u(s[np][0], s[np][2]));
                h8 = hadd2u(h8, hadd2u(s[np][1], s[np][3]));
            }
            float2 f0 = __half22float2(*(__half2*)&hg);
            float2 f1 = __half22float2(*(__half2*)&h8);
            l32[0] += f0.x + f0.y;
            l32[1] += f1.x + f1.y;
        }

        // ---- Phase 3: O += P.V, all 4 np chunks ----
#pragma unroll
        for (int np = 0; np < 4; np++) {
#pragma unroll
            for (int vc = 0; vc < 4; vc++) {
                uint32_t vb[4];
                LDSM4T(vb, vbase + 2 * (((np << 4) + qrow_l) * 72 + (vc << 4) + qcol_l));
                mma_f16(o[(vc << 1) + 0], s[np], vb[0], vb[1]);
                mma_f16(o[(vc << 1) + 1], s[np], vb[2], vb[3]);
            }
        }

        if (tk < kTilesPerSplit - 1) {
            CP_WAIT0();
            __syncthreads();
        }
    }

    // reduce l over the 4 t-lanes sharing each row
#pragma unroll
    for (int rc = 0; rc < 2; rc++) {
        l32[rc] += __shfl_xor_sync(0xffffffffu, l32[rc], 1);
        l32[rc] += __shfl_xor_sync(0xffffffffu, l32[rc], 2);
    }

    // store unnormalized partials
    float* pbase = g_po + ((size_t)sp * kRows + (size_t)bh * kNQ + q0) * kHD;
    {
        const int r0 = wr + g;
        float* rp = pbase + r0 * kHD;
#pragma unroll
        for (int nf = 0; nf < 8; nf++) {
            const int d = (nf << 3) + tq2;
            *(float2*)(rp + d) = make_float2(o[nf][0], o[nf][1]);
            *(float2*)(rp + 8 * kHD + d) = make_float2(o[nf][2], o[nf][3]);
        }
        if ((lane & 3) == 0) {
            g_pl[(size_t)sp * kRows + (size_t)bh * kNQ + q0 + r0] = l32[0];
            g_pl[(size_t)sp * kRows + (size_t)bh * kNQ + q0 + r0 + 8] = l32[1];
        }
    }
}

// ---------------------------------------------------------------------------
// Combine: sum split partials, normalize, write fp16 g_oh [b,nq,h*64+d]
// ---------------------------------------------------------------------------
__global__ __launch_bounds__(256) void combine_kernel()
{
    const int idx = blockIdx.x * 256 + threadIdx.x;
    const int row = idx >> 4;
    const int d4 = (idx & 15) << 2;

    float4 acc = make_float4(0.f, 0.f, 0.f, 0.f);
    float l = 0.f;
#pragma unroll
    for (int s = 0; s < kSplits; s++) {
        const float4 v = *(const float4*)(g_po + ((size_t)s * kRows + row) * kHD + d4);
        acc.x += v.x; acc.y += v.y; acc.z += v.z; acc.w += v.w;
        l += g_pl[(size_t)s * kRows + row];
    }
    const float inv = 1.0f / l;
    const int bh = row >> 10, iq = row & 1023;
    const int b = bh >> 3, h = bh & 7;
    __half2 h0 = __floats2half2_rn(acc.x * inv, acc.y * inv);
    __half2 h1 = __floats2half2_rn(acc.z * inv, acc.w * inv);
    __half* dst = g_oh + ((size_t)(b * kNQ) + iq) * kD + (h << 6) + d4;
    uint2 u;
    u.x = *(uint32_t*)&h0; u.y = *(uint32_t*)&h1;
    *(uint2*)dst = u;
}

// ---------------------------------------------------------------------------
extern "C" void kernel_launch(void* const* d_in, const int* in_sizes, int n_in,
                              void* d_out, int out_size)
{
    const float* x    = (const float*)d_in[0];
    const float* ctx  = (const float*)d_in[1];
    const float* Wq   = (const float*)d_in[2];
    const float* Wkv  = (const float*)d_in[3];
    const float* Wout = (const float*)d_in[4];
    const float* bout = (const float*)d_in[5];
    float* out = (float*)d_out;

    cudaFuncSetAttribute(attn_mma, cudaFuncAttributeMaxDynamicSharedMemorySize, AT_SMEM);

    // resolve device-global addresses (never pass __device__ symbols from host)
    __half *xh, *ctxh, *wqh, *wkvh, *wouth, *oh;
    cudaGetSymbolAddress((void**)&xh,    g_xh);
    cudaGetSymbolAddress((void**)&ctxh,  g_ctxh);
    cudaGetSymbolAddress((void**)&wqh,   g_wqh);
    cudaGetSymbolAddress((void**)&wkvh,  g_wkvh);
    cudaGetSymbolAddress((void**)&wouth, g_wouth);
    cudaGetSymbolAddress((void**)&oh,    g_oh);

    // fp32 -> fp16 pre-conversion
    cvt_f2h<<<(kB * kNQ * kD / 8 + 255) / 256, 256>>>(x, xh, kB * kNQ * kD / 8);
    cvt_f2h<<<(kB * kNC * kD / 8 + 255) / 256, 256>>>(ctx, ctxh, kB * kNC * kD / 8);
    cvt_weights<<<512, 256>>>(Wq, Wkv, Wout);

    // q = x @ Wq -> g_qh
    hgemm<0><<<dim3(32, 4), 256>>>(xh, wqh, nullptr, nullptr);
    // kv = ctx @ Wkv -> g_kh, g_vh (n-fastest grid)
    hgemm<1><<<dim3(8, 256), 256>>>(ctxh, wkvh, nullptr, nullptr);
    // flash attention split-KV (8 warps x 16 q-rows) -> g_po, g_pl
    attn_mma<<<dim3(8, 32, kSplits), 256, AT_SMEM>>>();
    // combine partials -> g_oh
    combine_kernel<<<2048, 256>>>();
    // out = g_oh @ Wout + bout
    hgemm<2><<<dim3(32, 4), 256>>>(oh, wouth, bout, out);
}

// round 15
// speedup vs baseline: 1.0152x; 1.0152x over previous
#include <cuda_runtime.h>
#include <cuda_fp16.h>
#include <stdint.h>

// Problem constants
constexpr int kB  = 4;
constexpr int kH  = 8;
constexpr int kNQ = 1024;
constexpr int kNC = 8192;
constexpr int kD  = 512;
constexpr int kHD = 64;
constexpr int kSplits = 4;
constexpr int kRows = kB * kH * kNQ;   // 32768

// Q pre-scale: 1/sqrt(64) * log2(e)
constexpr float kQScale = 0.18033688011112042f;

// Scratch (allocation is forbidden; use device globals)
__device__ __align__(16) __half g_xh  [kB * kNQ * kD];        //  4 MB fp16 x
__device__ __align__(16) __half g_ctxh[kB * kNC * kD];        // 32 MB fp16 context
__device__ __align__(16) __half g_wqh [kD * kD];              // fp16 Wq
__device__ __align__(16) __half g_wkvh[kD * 2 * kD];          // fp16 Wkv
__device__ __align__(16) __half g_wouth[kD * kD];             // fp16 Wout
__device__ __align__(16) __half g_qh[kB * kH * kNQ * kHD];    //  4 MB scaled fp16 q
__device__ __align__(16) __half g_kh[kB * kH * kNC * kHD];    // 32 MB fp16 k
__device__ __align__(16) __half g_vh[kB * kH * kNC * kHD];    // 32 MB fp16 v
__device__ __align__(16) float  g_po[kSplits * kRows * kHD];  // 32 MB O partials
__device__ __align__(16) float  g_pl[kSplits * kRows];        // l partials

// ---------------------------------------------------------------------------
// Helpers
// ---------------------------------------------------------------------------
__device__ __forceinline__ uint32_t smem_u32(const void* p) {
    uint32_t a;
    asm("{ .reg .u64 t; cvta.to.shared.u64 t, %1; cvt.u32.u64 %0, t; }"
        : "=r"(a) : "l"(p));
    return a;
}
#define CP16(dst_u32, src_ptr) \
    asm volatile("cp.async.cg.shared.global [%0], [%1], 16;" \
                 :: "r"(dst_u32), "l"(src_ptr) : "memory")
#define CP_COMMIT() asm volatile("cp.async.commit_group;" ::: "memory")
#define CP_WAIT0()  asm volatile("cp.async.wait_group 0;" ::: "memory")

#define LDSM4(r, addr) \
    asm volatile("ldmatrix.sync.aligned.m8n8.x4.shared.b16 {%0,%1,%2,%3}, [%4];" \
                 : "=r"((r)[0]), "=r"((r)[1]), "=r"((r)[2]), "=r"((r)[3]) : "r"(addr))
#define LDSM4T(r, addr) \
    asm volatile("ldmatrix.sync.aligned.m8n8.x4.trans.shared.b16 {%0,%1,%2,%3}, [%4];" \
                 : "=r"((r)[0]), "=r"((r)[1]), "=r"((r)[2]), "=r"((r)[3]) : "r"(addr))

// m16n8k16 fp16 mma, fp32 accumulate.
__device__ __forceinline__ void mma_f16(float d[4], const uint32_t a[4],
                                        uint32_t b0, uint32_t b1)
{
    asm volatile(
        "mma.sync.aligned.m16n8k16.row.col.f32.f16.f16.f32 "
        "{%0,%1,%2,%3}, {%4,%5,%6,%7}, {%8,%9}, {%0,%1,%2,%3};"
        : "+f"(d[0]), "+f"(d[1]), "+f"(d[2]), "+f"(d[3])
        : "r"(a[0]), "r"(a[1]), "r"(a[2]), "r"(a[3]), "r"(b0), "r"(b1));
}

// m16n8k16 fp16 mma, fp16 accumulate; d points at 2 u32 (4 halves).
__device__ __forceinline__ void mma_f16acc(uint32_t* d, const uint32_t a[4],
                                           uint32_t b0, uint32_t b1)
{
    asm volatile(
        "mma.sync.aligned.m16n8k16.row.col.f16.f16.f16.f16 "
        "{%0,%1}, {%2,%3,%4,%5}, {%6,%7}, {%0,%1};"
        : "+r"(d[0]), "+r"(d[1])
        : "r"(a[0]), "r"(a[1]), "r"(a[2]), "r"(a[3]), "r"(b0), "r"(b1));
}

// 2^x on packed f16x2
__device__ __forceinline__ uint32_t ex2u(uint32_t u) {
    uint32_t r;
    asm("ex2.approx.f16x2 %0, %1;" : "=r"(r) : "r"(u));
    return r;
}
__device__ __forceinline__ uint32_t hadd2u(uint32_t a, uint32_t b) {
    uint32_t r;
    asm("add.f16x2 %0, %1, %2;" : "=r"(r) : "r"(a), "r"(b));
    return r;
}

// ---------------------------------------------------------------------------
// fp32 -> fp16 bulk converts
// ---------------------------------------------------------------------------
__device__ __forceinline__ void cvt8(const float* __restrict__ s,
                                     __half* __restrict__ d, size_t i) {
    float4 a = *(const float4*)(s + i * 8);
    float4 b = *(const float4*)(s + i * 8 + 4);
    __half2 h[4];
    h[0] = __floats2half2_rn(a.x, a.y);
    h[1] = __floats2half2_rn(a.z, a.w);
    h[2] = __floats2half2_rn(b.x, b.y);
    h[3] = __floats2half2_rn(b.z, b.w);
    *(uint4*)(d + i * 8) = *(uint4*)h;
}

__global__ __launch_bounds__(256) void cvt_f2h(
    const float* __restrict__ src, __half* __restrict__ dst, int n8)
{
    const int i = blockIdx.x * 256 + threadIdx.x;
    if (i < n8) cvt8(src, dst, (size_t)i);
}

// All three weights in one launch
__global__ __launch_bounds__(256) void cvt_weights(
    const float* __restrict__ wq, const float* __restrict__ wkv,
    const float* __restrict__ wout)
{
    const int i = blockIdx.x * 256 + threadIdx.x;   // 0..131071
    if (i < 32768) {
        cvt8(wq, g_wqh, (size_t)i);
    } else if (i < 98304) {
        cvt8(wkv, g_wkvh, (size_t)(i - 32768));
    } else {
        cvt8(wout, g_wouth, (size_t)(i - 98304));
    }
}

// ---------------------------------------------------------------------------
// Pure-fp16 tensor GEMM, CTA 128x128, 8 warps 2m x 4n, K chunks of 32,
// cp.async double-buffered staging.
// MODE 0: A=g_xh    B=g_wqh   -> g_qh (scaled fp16 scatter)
// MODE 1: A=g_ctxh  B=g_wkvh  -> g_kh/g_vh (fp16 scatter); grid n-fastest
// MODE 2: A = fused combine of g_po/g_pl (split-sum + normalize in staging),
//         B=g_wouth -> Cout fp32 (+bias)
// ---------------------------------------------------------------------------
template <int MODE>
__global__ __launch_bounds__(256) void hgemm(
    const __half* __restrict__ Ah, const __half* __restrict__ Bh,
    const float* __restrict__ bias, float* __restrict__ Cout)
{
    constexpr int N = (MODE == 1) ? 1024 : 512;
    __shared__ __align__(16) __half As[2][128 * 40];
    __shared__ __align__(16) __half Bs[2][32 * 136];

    const int tid = threadIdx.x, lane = tid & 31, wid = tid >> 5;
    const int g = lane >> 2, tq2 = (lane & 3) << 1;
    const int m0 = (MODE == 1 ? blockIdx.y : blockIdx.x) << 7;
    const int n0 = (MODE == 1 ? blockIdx.x : blockIdx.y) << 7;
    const int arow = (wid >> 2) << 6, bcol = (wid & 3) << 5;

    const uint32_t asb0 = smem_u32(As[0]), bsb0 = smem_u32(Bs[0]);
    const uint32_t asb1 = smem_u32(As[1]), bsb1 = smem_u32(Bs[1]);

    const int arow_l = (lane & 7) + ((lane >> 3) & 1) * 8;
    const int acol_l = ((lane >> 4) & 1) * 8;
    const int brow_l = (lane & 7) + ((lane >> 3) & 1) * 8;
    const int bcol_l = ((lane >> 4) & 1) * 8;

    const int ia0 = tid << 1;
    const int aR0 = ia0 >> 2,  aO0 = (ia0 & 3) << 3;        // seg rows equal:
    const int aO1 = ((ia0 + 1) & 3) << 3;                   // (ia0+1)>>2 == aR0
    const int bR0 = ia0 >> 4,  bO0 = (ia0 & 15) << 3;
    const int bR1 = (ia0 + 1) >> 4, bO1 = ((ia0 + 1) & 15) << 3;

    // MODE2 fused-combine state: this thread's A-row is fixed (m0+aR0).
    float inv_l[8];
    size_t rowbase = 0;
    if (MODE == 2) {
        const int m = m0 + aR0;
        const int b = m >> 10, iq = m & 1023;
        rowbase = (size_t)(b * kH) * kNQ + iq;
#pragma unroll
        for (int h = 0; h < 8; h++) {
            float l = 0.f;
#pragma unroll
            for (int s = 0; s < kSplits; s++)
                l += g_pl[(size_t)s * kRows + rowbase + (size_t)h * kNQ];
            inv_l[h] = 1.0f / l;
        }
    }

    auto stage = [&](int bufi, int k0) {
        const uint32_t ab = bufi ? asb1 : asb0;
        const uint32_t bb = bufi ? bsb1 : bsb0;
        if (MODE == 2) {
            __half* Abuf = As[bufi];
#pragma unroll
            for (int sg = 0; sg < 2; sg++) {
                const int off = sg ? aO1 : aO0;
                const int n = k0 + off;               // g_oh column = h*64+d
                const int h = n >> 6, d0 = n & 63;
                const float* src = g_po + (rowbase + (size_t)h * kNQ) * kHD + d0;
                float4 u = make_float4(0.f, 0.f, 0.f, 0.f);
                float4 v = make_float4(0.f, 0.f, 0.f, 0.f);
#pragma unroll
                for (int s = 0; s < kSplits; s++) {
                    const float* p = src + (size_t)s * kRows * kHD;
                    float4 a4 = *(const float4*)p;
                    float4 b4 = *(const float4*)(p + 4);
                    u.x += a4.x; u.y += a4.y; u.z += a4.z; u.w += a4.w;
                    v.x += b4.x; v.y += b4.y; v.z += b4.z; v.w += b4.w;
                }
                const float il = inv_l[h];
                __half2 hh[4];
                hh[0] = __floats2half2_rn(u.x * il, u.y * il);
                hh[1] = __floats2half2_rn(u.z * il, u.w * il);
                hh[2] = __floats2half2_rn(v.x * il, v.y * il);
                hh[3] = __floats2half2_rn(v.z * il, v.w * il);
                *(uint4*)(Abuf + aR0 * 40 + off) = *(uint4*)hh;
            }
        } else {
            CP16(ab + 2 * (aR0 * 40 + aO0), Ah + (size_t)(m0 + aR0) * kD + k0 + aO0);
            CP16(ab + 2 * (aR0 * 40 + aO1), Ah + (size_t)(m0 + aR0) * kD + k0 + aO1);
        }
        CP16(bb + 2 * (bR0 * 136 + bO0), Bh + (size_t)(k0 + bR0) * N + n0 + bO0);
        CP16(bb + 2 * (bR1 * 136 + bO1), Bh + (size_t)(k0 + bR1) * N + n0 + bO1);
        CP_COMMIT();
    };

    stage(0, 0);

    float acc[4][4][4] = {};

    for (int c = 0; c < 16; c++) {
        const int cur = c & 1;
        CP_WAIT0();
        __syncthreads();
        if (c < 15)
            stage(1 - cur, (c + 1) << 5);
        const uint32_t asb = cur ? asb1 : asb0;
        const uint32_t bsb = cur ? bsb1 : bsb0;
#pragma unroll
        for (int h16 = 0; h16 < 2; h16++) {
            uint32_t a[4][4];
#pragma unroll
            for (int mf = 0; mf < 4; mf++)
                LDSM4(a[mf], asb + 2 * ((arow + (mf << 4) + arow_l) * 40 + (h16 << 4) + acol_l));
#pragma unroll
            for (int np = 0; np < 2; np++) {
                uint32_t b[4];
                LDSM4T(b, bsb + 2 * (((h16 << 4) + brow_l) * 136 + bcol + (np << 4) + bcol_l));
#pragma unroll
                for (int mf = 0; mf < 4; mf++) {
                    mma_f16(acc[mf][2 * np + 0], a[mf], b[0], b[1]);
                    mma_f16(acc[mf][2 * np + 1], a[mf], b[2], b[3]);
                }
            }
        }
    }

    // Epilogues
#pragma unroll
    for (int mf = 0; mf < 4; mf++) {
        const int m = m0 + arow + (mf << 4) + g;
#pragma unroll
        for (int nf = 0; nf < 4; nf++) {
            const int n = n0 + bcol + (nf << 3) + tq2;
            if (MODE == 0) {
                const int b_idx = m >> 10, iq = m & 1023;
                const int h = n >> 6, d = n & 63;
                __half* p0 = g_qh + (((size_t)(b_idx * kH + h) * kNQ + iq) << 6) + d;
                *(__half2*)p0 = __floats2half2_rn(acc[mf][nf][0] * kQScale,
                                                  acc[mf][nf][1] * kQScale);
                *(__half2*)(p0 + 512) = __floats2half2_rn(acc[mf][nf][2] * kQScale,
                                                          acc[mf][nf][3] * kQScale);
            } else if (MODE == 1) {
                const int bi = m >> 13, ic = m & 8191;
                __half* dst = (n < kD) ? g_kh : g_vh;
                const int h = (n >> 6) & 7, d = n & 63;
                __half* p0 = dst + (((size_t)(bi * kH + h) * kNC + ic) << 6) + d;
                *(__half2*)p0 = __floats2half2_rn(acc[mf][nf][0], acc[mf][nf][1]);
                *(__half2*)(p0 + 512) = __floats2half2_rn(acc[mf][nf][2], acc[mf][nf][3]);
            } else {
                const float b0 = bias[n], b1 = bias[n + 1];
                *(float2*)(Cout + (size_t)m * kD + n) =
                    make_float2(acc[mf][nf][0] + b0, acc[mf][nf][1] + b1);
                *(float2*)(Cout + (size_t)(m + 8) * kD + n) =
                    make_float2(acc[mf][nf][2] + b0, acc[mf][nf][3] + b1);
            }
        }
    }
}

// ---------------------------------------------------------------------------
// Flash attention, split-KV, phase-batched (R12 config: 4 warps x 32 q-rows,
// kv-tile 64, 128 threads). Per kv tile:
//   [all-S: f16acc mma] -> [ex2 f16x2] -> [all-PV: f32acc mma]
// l via HADD2 trees (off the tensor pipe), f32 accumulation.
// ---------------------------------------------------------------------------
constexpr int H_K0 = 0;
constexpr int H_V0 = 4608;
constexpr int H_K1 = 9216;
constexpr int H_V1 = 13824;
constexpr int AT_SMEM = 18432 * 2;   // 36864 bytes
constexpr int kTilesPerSplit = kNC / 64 / kSplits;   // 32

__global__ __launch_bounds__(128) void attn_mma()
{
    extern __shared__ __align__(16) __half sh[];
    const uint32_t sb = smem_u32(sh);

    const int tid = threadIdx.x, lane = tid & 31, wid = tid >> 5;
    const int g = lane >> 2, tq2 = (lane & 3) << 1;
    const int wr = wid << 5;
    const int bh = blockIdx.y, q0 = blockIdx.x << 7, sp = blockIdx.z;
    const int c0 = sp * kTilesPerSplit * 64;

    const __half* Qg = g_qh + ((size_t)bh * kNQ + q0) * kHD;
    const __half* Kg = g_kh + (size_t)bh * kNC * kHD + (size_t)c0 * kHD;
    const __half* Vg = g_vh + (size_t)bh * kNC * kHD + (size_t)c0 * kHD;

    const int qrow_l = (lane & 7) + ((lane >> 3) & 1) * 8;   // V rows (trans ldsm)
    const int qcol_l = ((lane >> 4) & 1) * 8;
    const int krow_l = (lane & 7) + ((lane >> 4) & 1) * 8;   // K (B) n-rows
    const int kcol_l = ((lane >> 3) & 1) * 8;

    // Stage K/V tile 0
#pragma unroll
    for (int p = 0; p < 4; p++) {
        int c = tid + (p << 7);
        int row = c >> 3, seg = (c & 7) << 3;
        CP16(sb + 2 * (H_K0 + row * 72 + seg), Kg + (row << 6) + seg);
        CP16(sb + 2 * (H_V0 + row * 72 + seg), Vg + (row << 6) + seg);
    }
    CP_COMMIT();

    // Q fragments straight from gmem
    uint32_t qa[2][4][4];
#pragma unroll
    for (int mf = 0; mf < 2; mf++)
#pragma unroll
        for (int kc = 0; kc < 4; kc++) {
            const __half* qp = Qg + (wr + (mf << 4) + g) * kHD + (kc << 4) + tq2;
            qa[mf][kc][0] = *(const uint32_t*)qp;
            qa[mf][kc][1] = *(const uint32_t*)(qp + 8 * kHD);
            qa[mf][kc][2] = *(const uint32_t*)(qp + 8);
            qa[mf][kc][3] = *(const uint32_t*)(qp + 8 * kHD + 8);
        }

    float o[2][8][4] = {};
    float l32[2][2] = {};   // [mf][row-class g / g+8]

    CP_WAIT0();
    __syncthreads();

    for (int tk = 0; tk < kTilesPerSplit; tk++) {
        const int cur = tk & 1;
        if (tk < kTilesPerSplit - 1) {
            const __half* Kt = Kg + (size_t)(tk + 1) * 64 * kHD;
            const __half* Vt = Vg + (size_t)(tk + 1) * 64 * kHD;
            const int kd = cur ? H_K0 : H_K1;
            const int vd = cur ? H_V0 : H_V1;
#pragma unroll
            for (int p = 0; p < 4; p++) {
                int c = tid + (p << 7);
                int row = c >> 3, seg = (c & 7) << 3;
                CP16(sb + 2 * (kd + row * 72 + seg), Kt + (row << 6) + seg);
                CP16(sb + 2 * (vd + row * 72 + seg), Vt + (row << 6) + seg);
            }
            CP_COMMIT();
        }
        const uint32_t kbase = sb + 2 * (cur ? H_K1 : H_K0);
        const uint32_t vbase = sb + 2 * (cur ? H_V1 : H_V0);

        // ---- Phase 1: S = Q.K^T (fp16 acc) for ALL 4 np chunks ----
        uint32_t s[4][2][4] = {};
#pragma unroll
        for (int np = 0; np < 4; np++) {
#pragma unroll
            for (int kc = 0; kc < 4; kc++) {
                uint32_t kb[4];
                LDSM4(kb, kbase + 2 * (((np << 4) + krow_l) * 72 + (kc << 4) + kcol_l));
                mma_f16acc(&s[np][0][0], qa[0][kc], kb[0], kb[1]);
                mma_f16acc(&s[np][1][0], qa[1][kc], kb[0], kb[1]);
                mma_f16acc(&s[np][0][2], qa[0][kc], kb[2], kb[3]);
                mma_f16acc(&s[np][1][2], qa[1][kc], kb[2], kb[3]);
            }
        }

        // ---- Phase 2: exp2 in place ----
#pragma unroll
        for (int np = 0; np < 4; np++)
#pragma unroll
            for (int mf = 0; mf < 2; mf++) {
                s[np][mf][0] = ex2u(s[np][mf][0]);
                s[np][mf][1] = ex2u(s[np][mf][1]);
                s[np][mf][2] = ex2u(s[np][mf][2]);
                s[np][mf][3] = ex2u(s[np][mf][3]);
            }

        // ---- l: HADD2 trees (regs 0,2 = row g; 1,3 = row g+8) ----
#pragma unroll
        for (int mf = 0; mf < 2; mf++) {
            uint32_t hg  = hadd2u(hadd2u(s[0][mf][0], s[0][mf][2]),
                                  hadd2u(s[1][mf][0], s[1][mf][2]));
            hg = hadd2u(hg, hadd2u(hadd2u(s[2][mf][0], s[2][mf][2]),
                                   hadd2u(s[3][mf][0], s[3][mf][2])));
            uint32_t hg8 = hadd2u(hadd2u(s[0][mf][1], s[0][mf][3]),
                                  hadd2u(s[1][mf][1], s[1][mf][3]));
            hg8 = hadd2u(hg8, hadd2u(hadd2u(s[2][mf][1], s[2][mf][3]),
                                     hadd2u(s[3][mf][1], s[3][mf][3])));
            float2 f0 = __half22float2(*(__half2*)&hg);
            float2 f1 = __half22float2(*(__half2*)&hg8);
            l32[mf][0] += f0.x + f0.y;
            l32[mf][1] += f1.x + f1.y;
        }

        // ---- Phase 3: O += P.V for ALL 4 np chunks ----
#pragma unroll
        for (int np = 0; np < 4; np++) {
#pragma unroll
            for (int vc = 0; vc < 4; vc++) {
                uint32_t vb[4];
                LDSM4T(vb, vbase + 2 * (((np << 4) + qrow_l) * 72 + (vc << 4) + qcol_l));
                mma_f16(o[0][(vc << 1) + 0], s[np][0], vb[0], vb[1]);
                mma_f16(o[1][(vc << 1) + 0], s[np][1], vb[0], vb[1]);
                mma_f16(o[0][(vc << 1) + 1], s[np][0], vb[2], vb[3]);
                mma_f16(o[1][(vc << 1) + 1], s[np][1], vb[2], vb[3]);
            }
        }

        if (tk < kTilesPerSplit - 1) {
            CP_WAIT0();
            __syncthreads();
        }
    }

    // reduce l over the 4 t-lanes sharing each row
#pragma unroll
    for (int mf = 0; mf < 2; mf++)
#pragma unroll
        for (int rc = 0; rc < 2; rc++) {
            l32[mf][rc] += __shfl_xor_sync(0xffffffffu, l32[mf][rc], 1);
            l32[mf][rc] += __shfl_xor_sync(0xffffffffu, l32[mf][rc], 2);
        }

    // store unnormalized partials
    float* pbase = g_po + ((size_t)sp * kRows + (size_t)bh * kNQ + q0) * kHD;
#pragma unroll
    for (int mf = 0; mf < 2; mf++) {
        const int r0 = wr + (mf << 4) + g;
        float* rp = pbase + r0 * kHD;
#pragma unroll
        for (int nf = 0; nf < 8; nf++) {
            const int d = (nf << 3) + tq2;
            *(float2*)(rp + d) = make_float2(o[mf][nf][0], o[mf][nf][1]);
            *(float2*)(rp + 8 * kHD + d) = make_float2(o[mf][nf][2], o[mf][nf][3]);
        }
        if ((lane & 3) == 0) {
            g_pl[(size_t)sp * kRows + (size_t)bh * kNQ + q0 + r0] = l32[mf][0];
            g_pl[(size_t)sp * kRows + (size_t)bh * kNQ + q0 + r0 + 8] = l32[mf][1];
        }
    }
}

// ---------------------------------------------------------------------------
extern "C" void kernel_launch(void* const* d_in, const int* in_sizes, int n_in,
                              void* d_out, int out_size)
{
    const float* x    = (const float*)d_in[0];
    const float* ctx  = (const float*)d_in[1];
    const float* Wq   = (const float*)d_in[2];
    const float* Wkv  = (const float*)d_in[3];
    const float* Wout = (const float*)d_in[4];
    const float* bout = (const float*)d_in[5];
    float* out = (float*)d_out;

    cudaFuncSetAttribute(attn_mma, cudaFuncAttributeMaxDynamicSharedMemorySize, AT_SMEM);

    // resolve device-global addresses (never pass __device__ symbols from host)
    __half *xh, *ctxh, *wqh, *wkvh, *wouth;
    cudaGetSymbolAddress((void**)&xh,    g_xh);
    cudaGetSymbolAddress((void**)&ctxh,  g_ctxh);
    cudaGetSymbolAddress((void**)&wqh,   g_wqh);
    cudaGetSymbolAddress((void**)&wkvh,  g_wkvh);
    cudaGetSymbolAddress((void**)&wouth, g_wouth);

    // fp32 -> fp16 pre-conversion
    cvt_f2h<<<(kB * kNQ * kD / 8 + 255) / 256, 256>>>(x, xh, kB * kNQ * kD / 8);
    cvt_f2h<<<(kB * kNC * kD / 8 + 255) / 256, 256>>>(ctx, ctxh, kB * kNC * kD / 8);
    cvt_weights<<<512, 256>>>(Wq, Wkv, Wout);

    // q = x @ Wq -> g_qh
    hgemm<0><<<dim3(32, 4), 256>>>(xh, wqh, nullptr, nullptr);
    // kv = ctx @ Wkv -> g_kh, g_vh (n-fastest grid)
    hgemm<1><<<dim3(8, 256), 256>>>(ctxh, wkvh, nullptr, nullptr);
    // flash attention split-KV -> g_po, g_pl
    attn_mma<<<dim3(8, 32, kSplits), 128, AT_SMEM>>>();
    // out = combine(g_po, g_pl) @ Wout + bout  (combine fused into A staging)
    hgemm<2><<<dim3(32, 4), 256>>>(nullptr, wouth, bout, out);
}

// round 16
// speedup vs baseline: 1.0904x; 1.0741x over previous
#include <cuda_runtime.h>
#include <cuda_fp16.h>
#include <stdint.h>

// Problem constants
constexpr int kB  = 4;
constexpr int kH  = 8;
constexpr int kNQ = 1024;
constexpr int kNC = 8192;
constexpr int kD  = 512;
constexpr int kHD = 64;
constexpr int kSplits = 4;
constexpr int kRows = kB * kH * kNQ;   // 32768

// Q pre-scale: 1/sqrt(64) * log2(e)
constexpr float kQScale = 0.18033688011112042f;

// Scratch (allocation is forbidden; use device globals)
__device__ __align__(16) __half g_xh  [kB * kNQ * kD];        //  4 MB fp16 x
__device__ __align__(16) __half g_ctxh[kB * kNC * kD];        // 32 MB fp16 context
__device__ __align__(16) __half g_wqh [kD * kD];              // fp16 Wq
__device__ __align__(16) __half g_wkvh[kD * 2 * kD];          // fp16 Wkv
__device__ __align__(16) __half g_wouth[kD * kD];             // fp16 Wout
__device__ __align__(16) __half g_qh[kB * kH * kNQ * kHD];    //  4 MB scaled fp16 q
__device__ __align__(16) __half g_kh[kB * kH * kNC * kHD];    // 32 MB fp16 k
__device__ __align__(16) __half g_vh[kB * kH * kNC * kHD];    // 32 MB fp16 v
__device__ __align__(16) __half g_oh[kB * kNQ * kD];          //  4 MB fp16 attn out
__device__ __align__(16) float  g_po[kSplits * kRows * kHD];  // 32 MB O partials
__device__ __align__(16) float  g_pl[kSplits * kRows];        // l partials

// ---------------------------------------------------------------------------
// Helpers
// ---------------------------------------------------------------------------
__device__ __forceinline__ uint32_t smem_u32(const void* p) {
    uint32_t a;
    asm("{ .reg .u64 t; cvta.to.shared.u64 t, %1; cvt.u32.u64 %0, t; }"
        : "=r"(a) : "l"(p));
    return a;
}
#define CP16(dst_u32, src_ptr) \
    asm volatile("cp.async.cg.shared.global [%0], [%1], 16;" \
                 :: "r"(dst_u32), "l"(src_ptr) : "memory")
#define CP_COMMIT() asm volatile("cp.async.commit_group;" ::: "memory")
#define CP_WAIT0()  asm volatile("cp.async.wait_group 0;" ::: "memory")

#define LDSM4(r, addr) \
    asm volatile("ldmatrix.sync.aligned.m8n8.x4.shared.b16 {%0,%1,%2,%3}, [%4];" \
                 : "=r"((r)[0]), "=r"((r)[1]), "=r"((r)[2]), "=r"((r)[3]) : "r"(addr))
#define LDSM4T(r, addr) \
    asm volatile("ldmatrix.sync.aligned.m8n8.x4.trans.shared.b16 {%0,%1,%2,%3}, [%4];" \
                 : "=r"((r)[0]), "=r"((r)[1]), "=r"((r)[2]), "=r"((r)[3]) : "r"(addr))

// m16n8k16 fp16 mma, fp32 accumulate.
__device__ __forceinline__ void mma_f16(float d[4], const uint32_t a[4],
                                        uint32_t b0, uint32_t b1)
{
    asm volatile(
        "mma.sync.aligned.m16n8k16.row.col.f32.f16.f16.f32 "
        "{%0,%1,%2,%3}, {%4,%5,%6,%7}, {%8,%9}, {%0,%1,%2,%3};"
        : "+f"(d[0]), "+f"(d[1]), "+f"(d[2]), "+f"(d[3])
        : "r"(a[0]), "r"(a[1]), "r"(a[2]), "r"(a[3]), "r"(b0), "r"(b1));
}

// m16n8k16 fp16 mma, fp16 accumulate; d points at 2 u32 (4 halves).
__device__ __forceinline__ void mma_f16acc(uint32_t* d, const uint32_t a[4],
                                           uint32_t b0, uint32_t b1)
{
    asm volatile(
        "mma.sync.aligned.m16n8k16.row.col.f16.f16.f16.f16 "
        "{%0,%1}, {%2,%3,%4,%5}, {%6,%7}, {%0,%1};"
        : "+r"(d[0]), "+r"(d[1])
        : "r"(a[0]), "r"(a[1]), "r"(a[2]), "r"(a[3]), "r"(b0), "r"(b1));
}

// 2^x on packed f16x2
__device__ __forceinline__ uint32_t ex2u(uint32_t u) {
    uint32_t r;
    asm("ex2.approx.f16x2 %0, %1;" : "=r"(r) : "r"(u));
    return r;
}
__device__ __forceinline__ uint32_t hadd2u(uint32_t a, uint32_t b) {
    uint32_t r;
    asm("add.f16x2 %0, %1, %2;" : "=r"(r) : "r"(a), "r"(b));
    return r;
}

// ---------------------------------------------------------------------------
// fp32 -> fp16 bulk convert, ALL tensors in one launch (range dispatch)
// segs: ctx 2097152 | x 262144 | wq 32768 | wkv 65536 | wout 32768 = 2490368
// ---------------------------------------------------------------------------
__device__ __forceinline__ void cvt8(const float* __restrict__ s,
                                     __half* __restrict__ d, size_t i) {
    float4 a = *(const float4*)(s + i * 8);
    float4 b = *(const float4*)(s + i * 8 + 4);
    __half2 h[4];
    h[0] = __floats2half2_rn(a.x, a.y);
    h[1] = __floats2half2_rn(a.z, a.w);
    h[2] = __floats2half2_rn(b.x, b.y);
    h[3] = __floats2half2_rn(b.z, b.w);
    *(uint4*)(d + i * 8) = *(uint4*)h;
}

__global__ __launch_bounds__(256) void cvt_all(
    const float* __restrict__ x, const float* __restrict__ ctx,
    const float* __restrict__ wq, const float* __restrict__ wkv,
    const float* __restrict__ wout)
{
    const size_t i = (size_t)blockIdx.x * 256 + threadIdx.x;
    if (i < 2097152)      cvt8(ctx,  g_ctxh,  i);
    else if (i < 2359296) cvt8(x,    g_xh,    i - 2097152);
    else if (i < 2392064) cvt8(wq,   g_wqh,   i - 2359296);
    else if (i < 2457600) cvt8(wkv,  g_wkvh,  i - 2392064);
    else                  cvt8(wout, g_wouth, i - 2457600);
}

// ---------------------------------------------------------------------------
// fp16 tensor GEMM body (dynamic smem): CTA 128x128, 8 warps 2m x 4n,
// K chunks of 32, cp.async double-buffered staging.
// MODE 0: A=g_xh   B=g_wqh   -> g_qh (scaled fp16 scatter)
// MODE 1: A=g_ctxh B=g_wkvh  -> g_kh/g_vh (fp16 scatter)
// MODE 2: A=g_oh   B=g_wouth -> Cout fp32 (+bias)
// smem layout: As[2][128*40] halves (20480 B) | Bs[2][32*136] halves (17408 B)
// ---------------------------------------------------------------------------
constexpr int HG_SMEM = (2 * 128 * 40 + 2 * 32 * 136) * 2;   // 37888 bytes

template <int MODE>
__device__ __forceinline__ void hgemm_body(
    char* smem, const __half* __restrict__ Ah, const __half* __restrict__ Bh,
    const float* __restrict__ bias, float* __restrict__ Cout, int m0, int n0)
{
    constexpr int N = (MODE == 1) ? 1024 : 512;
    __half* As0 = (__half*)smem;
    __half* As1 = As0 + 128 * 40;
    __half* Bs0 = As1 + 128 * 40;
    __half* Bs1 = Bs0 + 32 * 136;

    const int tid = threadIdx.x, lane = tid & 31, wid = tid >> 5;
    const int g = lane >> 2, tq2 = (lane & 3) << 1;
    const int arow = (wid >> 2) << 6, bcol = (wid & 3) << 5;

    const uint32_t asb0 = smem_u32(As0), bsb0 = smem_u32(Bs0);
    const uint32_t asb1 = smem_u32(As1), bsb1 = smem_u32(Bs1);

    const int arow_l = (lane & 7) + ((lane >> 3) & 1) * 8;
    const int acol_l = ((lane >> 4) & 1) * 8;
    const int brow_l = (lane & 7) + ((lane >> 3) & 1) * 8;
    const int bcol_l = ((lane >> 4) & 1) * 8;

    const int ia0 = tid << 1;
    const int aR0 = ia0 >> 2,  aO0 = (ia0 & 3) << 3;
    const int aR1 = (ia0 + 1) >> 2, aO1 = ((ia0 + 1) & 3) << 3;
    const int bR0 = ia0 >> 4,  bO0 = (ia0 & 15) << 3;
    const int bR1 = (ia0 + 1) >> 4, bO1 = ((ia0 + 1) & 15) << 3;

    auto stage = [&](uint32_t ab, uint32_t bb, int k0) {
        CP16(ab + 2 * (aR0 * 40 + aO0), Ah + (size_t)(m0 + aR0) * kD + k0 + aO0);
        CP16(ab + 2 * (aR1 * 40 + aO1), Ah + (size_t)(m0 + aR1) * kD + k0 + aO1);
        CP16(bb + 2 * (bR0 * 136 + bO0), Bh + (size_t)(k0 + bR0) * N + n0 + bO0);
        CP16(bb + 2 * (bR1 * 136 + bO1), Bh + (size_t)(k0 + bR1) * N + n0 + bO1);
        CP_COMMIT();
    };

    stage(asb0, bsb0, 0);

    float acc[4][4][4] = {};

    for (int c = 0; c < 16; c++) {
        const int cur = c & 1;
        CP_WAIT0();
        __syncthreads();
        if (c < 15)
            stage(cur ? asb0 : asb1, cur ? bsb0 : bsb1, (c + 1) << 5);
        const uint32_t asb = cur ? asb1 : asb0;
        const uint32_t bsb = cur ? bsb1 : bsb0;
#pragma unroll
        for (int h16 = 0; h16 < 2; h16++) {
            uint32_t a[4][4];
#pragma unroll
            for (int mf = 0; mf < 4; mf++)
                LDSM4(a[mf], asb + 2 * ((arow + (mf << 4) + arow_l) * 40 + (h16 << 4) + acol_l));
#pragma unroll
            for (int np = 0; np < 2; np++) {
                uint32_t b[4];
                LDSM4T(b, bsb + 2 * (((h16 << 4) + brow_l) * 136 + bcol + (np << 4) + bcol_l));
#pragma unroll
                for (int mf = 0; mf < 4; mf++) {
                    mma_f16(acc[mf][2 * np + 0], a[mf], b[0], b[1]);
                    mma_f16(acc[mf][2 * np + 1], a[mf], b[2], b[3]);
                }
            }
        }
    }

    // Epilogues
#pragma unroll
    for (int mf = 0; mf < 4; mf++) {
        const int m = m0 + arow + (mf << 4) + g;
#pragma unroll
        for (int nf = 0; nf < 4; nf++) {
            const int n = n0 + bcol + (nf << 3) + tq2;
            if (MODE == 0) {
                const int b_idx = m >> 10, iq = m & 1023;
                const int h = n >> 6, d = n & 63;
                __half* p0 = g_qh + (((size_t)(b_idx * kH + h) * kNQ + iq) << 6) + d;
                *(__half2*)p0 = __floats2half2_rn(acc[mf][nf][0] * kQScale,
                                                  acc[mf][nf][1] * kQScale);
                *(__half2*)(p0 + 512) = __floats2half2_rn(acc[mf][nf][2] * kQScale,
                                                          acc[mf][nf][3] * kQScale);
            } else if (MODE == 1) {
                const int bi = m >> 13, ic = m & 8191;
                __half* dst = (n < kD) ? g_kh : g_vh;
                const int h = (n >> 6) & 7, d = n & 63;
                __half* p0 = dst + (((size_t)(bi * kH + h) * kNC + ic) << 6) + d;
                *(__half2*)p0 = __floats2half2_rn(acc[mf][nf][0], acc[mf][nf][1]);
                *(__half2*)(p0 + 512) = __floats2half2_rn(acc[mf][nf][2], acc[mf][nf][3]);
            } else {
                const float b0 = bias[n], b1 = bias[n + 1];
                *(float2*)(Cout + (size_t)m * kD + n) =
                    make_float2(acc[mf][nf][0] + b0, acc[mf][nf][1] + b1);
                *(float2*)(Cout + (size_t)(m + 8) * kD + n) =
                    make_float2(acc[mf][nf][2] + b0, acc[mf][nf][3] + b1);
            }
        }
    }
}

// Fused q-proj + kv-proj: blocks [0,2048) = kv tiles (n-fastest), [2048,2176) = q.
__global__ __launch_bounds__(256) void qkv_gemm(
    const __half* __restrict__ xh, const __half* __restrict__ wqh,
    const __half* __restrict__ ctxh, const __half* __restrict__ wkvh)
{
    extern __shared__ __align__(16) char smem[];
    const int bid = blockIdx.x;
    if (bid < 2048) {
        hgemm_body<1>(smem, ctxh, wkvh, nullptr, nullptr,
                      (bid >> 3) << 7, (bid & 7) << 7);
    } else {
        const int b = bid - 2048;
        hgemm_body<0>(smem, xh, wqh, nullptr, nullptr,
                      (b >> 2) << 7, (b & 3) << 7);
    }
}

// Out-projection (reads g_oh produced by combine)
__global__ __launch_bounds__(256) void out_gemm(
    const __half* __restrict__ oh, const __half* __restrict__ wouth,
    const float* __restrict__ bias, float* __restrict__ out)
{
    extern __shared__ __align__(16) char smem[];
    hgemm_body<2>(smem, oh, wouth, bias, out,
                  (int)(blockIdx.x << 7), (int)(blockIdx.y << 7));
}

// ---------------------------------------------------------------------------
// Flash attention, split-KV, phase-batched (R12 config: 4 warps x 32 q-rows,
// kv-tile 64, 128 threads). Byte-identical math to the 352.3us baseline.
// ---------------------------------------------------------------------------
constexpr int H_K0 = 0;
constexpr int H_V0 = 4608;
constexpr int H_K1 = 9216;
constexpr int H_V1 = 13824;
constexpr int AT_SMEM = 18432 * 2;   // 36864 bytes
constexpr int kTilesPerSplit = kNC / 64 / kSplits;   // 32

__global__ __launch_bounds__(128) void attn_mma()
{
    extern __shared__ __align__(16) __half sh[];
    const uint32_t sb = smem_u32(sh);

    const int tid = threadIdx.x, lane = tid & 31, wid = tid >> 5;
    const int g = lane >> 2, tq2 = (lane & 3) << 1;
    const int wr = wid << 5;
    const int bh = blockIdx.y, q0 = blockIdx.x << 7, sp = blockIdx.z;
    const int c0 = sp * kTilesPerSplit * 64;

    const __half* Qg = g_qh + ((size_t)bh * kNQ + q0) * kHD;
    const __half* Kg = g_kh + (size_t)bh * kNC * kHD + (size_t)c0 * kHD;
    const __half* Vg = g_vh + (size_t)bh * kNC * kHD + (size_t)c0 * kHD;

    const int qrow_l = (lane & 7) + ((lane >> 3) & 1) * 8;   // V rows (trans ldsm)
    const int qcol_l = ((lane >> 4) & 1) * 8;
    const int krow_l = (lane & 7) + ((lane >> 4) & 1) * 8;   // K (B) n-rows
    const int kcol_l = ((lane >> 3) & 1) * 8;

    // Stage K/V tile 0
#pragma unroll
    for (int p = 0; p < 4; p++) {
        int c = tid + (p << 7);
        int row = c >> 3, seg = (c & 7) << 3;
        CP16(sb + 2 * (H_K0 + row * 72 + seg), Kg + (row << 6) + seg);
        CP16(sb + 2 * (H_V0 + row * 72 + seg), Vg + (row << 6) + seg);
    }
    CP_COMMIT();

    // Q fragments straight from gmem
    uint32_t qa[2][4][4];
#pragma unroll
    for (int mf = 0; mf < 2; mf++)
#pragma unroll
        for (int kc = 0; kc < 4; kc++) {
            const __half* qp = Qg + (wr + (mf << 4) + g) * kHD + (kc << 4) + tq2;
            qa[mf][kc][0] = *(const uint32_t*)qp;
            qa[mf][kc][1] = *(const uint32_t*)(qp + 8 * kHD);
            qa[mf][kc][2] = *(const uint32_t*)(qp + 8);
            qa[mf][kc][3] = *(const uint32_t*)(qp + 8 * kHD + 8);
        }

    float o[2][8][4] = {};
    float l32[2][2] = {};   // [mf][row-class g / g+8]

    CP_WAIT0();
    __syncthreads();

    for (int tk = 0; tk < kTilesPerSplit; tk++) {
        const int cur = tk & 1;
        if (tk < kTilesPerSplit - 1) {
            const __half* Kt = Kg + (size_t)(tk + 1) * 64 * kHD;
            const __half* Vt = Vg + (size_t)(tk + 1) * 64 * kHD;
            const int kd = cur ? H_K0 : H_K1;
            const int vd = cur ? H_V0 : H_V1;
#pragma unroll
            for (int p = 0; p < 4; p++) {
                int c = tid + (p << 7);
                int row = c >> 3, seg = (c & 7) << 3;
                CP16(sb + 2 * (kd + row * 72 + seg), Kt + (row << 6) + seg);
                CP16(sb + 2 * (vd + row * 72 + seg), Vt + (row << 6) + seg);
            }
            CP_COMMIT();
        }
        const uint32_t kbase = sb + 2 * (cur ? H_K1 : H_K0);
        const uint32_t vbase = sb + 2 * (cur ? H_V1 : H_V0);

        // ---- Phase 1: S = Q.K^T (fp16 acc) for ALL 4 np chunks ----
        uint32_t s[4][2][4] = {};
#pragma unroll
        for (int np = 0; np < 4; np++) {
#pragma unroll
            for (int kc = 0; kc < 4; kc++) {
                uint32_t kb[4];
                LDSM4(kb, kbase + 2 * (((np << 4) + krow_l) * 72 + (kc << 4) + kcol_l));
                mma_f16acc(&s[np][0][0], qa[0][kc], kb[0], kb[1]);
                mma_f16acc(&s[np][1][0], qa[1][kc], kb[0], kb[1]);
                mma_f16acc(&s[np][0][2], qa[0][kc], kb[2], kb[3]);
                mma_f16acc(&s[np][1][2], qa[1][kc], kb[2], kb[3]);
            }
        }

        // ---- Phase 2: exp2 in place ----
#pragma unroll
        for (int np = 0; np < 4; np++)
#pragma unroll
            for (int mf = 0; mf < 2; mf++) {
                s[np][mf][0] = ex2u(s[np][mf][0]);
                s[np][mf][1] = ex2u(s[np][mf][1]);
                s[np][mf][2] = ex2u(s[np][mf][2]);
                s[np][mf][3] = ex2u(s[np][mf][3]);
            }

        // ---- l: HADD2 trees (regs 0,2 = row g; 1,3 = row g+8) ----
#pragma unroll
        for (int mf = 0; mf < 2; mf++) {
            uint32_t hg  = hadd2u(hadd2u(s[0][mf][0], s[0][mf][2]),
                                  hadd2u(s[1][mf][0], s[1][mf][2]));
            hg = hadd2u(hg, hadd2u(hadd2u(s[2][mf][0], s[2][mf][2]),
                                   hadd2u(s[3][mf][0], s[3][mf][2])));
            uint32_t hg8 = hadd2u(hadd2u(s[0][mf][1], s[0][mf][3]),
                                  hadd2u(s[1][mf][1], s[1][mf][3]));
            hg8 = hadd2u(hg8, hadd2u(hadd2u(s[2][mf][1], s[2][mf][3]),
                                     hadd2u(s[3][mf][1], s[3][mf][3])));
            float2 f0 = __half22float2(*(__half2*)&hg);
            float2 f1 = __half22float2(*(__half2*)&hg8);
            l32[mf][0] += f0.x + f0.y;
            l32[mf][1] += f1.x + f1.y;
        }

        // ---- Phase 3: O += P.V for ALL 4 np chunks ----
#pragma unroll
        for (int np = 0; np < 4; np++) {
#pragma unroll
            for (int vc = 0; vc < 4; vc++) {
                uint32_t vb[4];
                LDSM4T(vb, vbase + 2 * (((np << 4) + qrow_l) * 72 + (vc << 4) + qcol_l));
                mma_f16(o[0][(vc << 1) + 0], s[np][0], vb[0], vb[1]);
                mma_f16(o[1][(vc << 1) + 0], s[np][1], vb[0], vb[1]);
                mma_f16(o[0][(vc << 1) + 1], s[np][0], vb[2], vb[3]);
                mma_f16(o[1][(vc << 1) + 1], s[np][1], vb[2], vb[3]);
            }
        }

        if (tk < kTilesPerSplit - 1) {
            CP_WAIT0();
            __syncthreads();
        }
    }

    // reduce l over the 4 t-lanes sharing each row
#pragma unroll
    for (int mf = 0; mf < 2; mf++)
#pragma unroll
        for (int rc = 0; rc < 2; rc++) {
            l32[mf][rc] += __shfl_xor_sync(0xffffffffu, l32[mf][rc], 1);
            l32[mf][rc] += __shfl_xor_sync(0xffffffffu, l32[mf][rc], 2);
        }

    // store unnormalized partials
    float* pbase = g_po + ((size_t)sp * kRows + (size_t)bh * kNQ + q0) * kHD;
#pragma unroll
    for (int mf = 0; mf < 2; mf++) {
        const int r0 = wr + (mf << 4) + g;
        float* rp = pbase + r0 * kHD;
#pragma unroll
        for (int nf = 0; nf < 8; nf++) {
            const int d = (nf << 3) + tq2;
            *(float2*)(rp + d) = make_float2(o[mf][nf][0], o[mf][nf][1]);
            *(float2*)(rp + 8 * kHD + d) = make_float2(o[mf][nf][2], o[mf][nf][3]);
        }
        if ((lane & 3) == 0) {
            g_pl[(size_t)sp * kRows + (size_t)bh * kNQ + q0 + r0] = l32[mf][0];
            g_pl[(size_t)sp * kRows + (size_t)bh * kNQ + q0 + r0 + 8] = l32[mf][1];
        }
    }
}

// ---------------------------------------------------------------------------
// Combine: sum split partials, normalize, write fp16 g_oh [b,nq,h*64+d]
// ---------------------------------------------------------------------------
__global__ __launch_bounds__(256) void combine_kernel()
{
    const int idx = blockIdx.x * 256 + threadIdx.x;
    const int row = idx >> 4;
    const int d4 = (idx & 15) << 2;

    float4 acc = make_float4(0.f, 0.f, 0.f, 0.f);
    float l = 0.f;
#pragma unroll
    for (int s = 0; s < kSplits; s++) {
        const float4 v = *(const float4*)(g_po + ((size_t)s * kRows + row) * kHD + d4);
        acc.x += v.x; acc.y += v.y; acc.z += v.z; acc.w += v.w;
        l += g_pl[(size_t)s * kRows + row];
    }
    const float inv = 1.0f / l;
    const int bh = row >> 10, iq = row & 1023;
    const int b = bh >> 3, h = bh & 7;
    __half2 h0 = __floats2half2_rn(acc.x * inv, acc.y * inv);
    __half2 h1 = __floats2half2_rn(acc.z * inv, acc.w * inv);
    __half* dst = g_oh + ((size_t)(b * kNQ) + iq) * kD + (h << 6) + d4;
    uint2 u;
    u.x = *(uint32_t*)&h0; u.y = *(uint32_t*)&h1;
    *(uint2*)dst = u;
}

// ---------------------------------------------------------------------------
extern "C" void kernel_launch(void* const* d_in, const int* in_sizes, int n_in,
                              void* d_out, int out_size)
{
    const float* x    = (const float*)d_in[0];
    const float* ctx  = (const float*)d_in[1];
    const float* Wq   = (const float*)d_in[2];
    const float* Wkv  = (const float*)d_in[3];
    const float* Wout = (const float*)d_in[4];
    const float* bout = (const float*)d_in[5];
    float* out = (float*)d_out;

    cudaFuncSetAttribute(attn_mma, cudaFuncAttributeMaxDynamicSharedMemorySize, AT_SMEM);

    // resolve device-global addresses (never pass __device__ symbols from host)
    __half *xh, *ctxh, *wqh, *wkvh, *wouth, *oh;
    cudaGetSymbolAddress((void**)&xh,    g_xh);
    cudaGetSymbolAddress((void**)&ctxh,  g_ctxh);
    cudaGetSymbolAddress((void**)&wqh,   g_wqh);
    cudaGetSymbolAddress((void**)&wkvh,  g_wkvh);
    cudaGetSymbolAddress((void**)&wouth, g_wouth);
    cudaGetSymbolAddress((void**)&oh,    g_oh);

    // all fp32 -> fp16 conversions in ONE launch
    cvt_all<<<9728, 256>>>(x, ctx, Wq, Wkv, Wout);
    // q-proj + kv-proj fused into ONE launch (kv blocks first = long pole)
    qkv_gemm<<<2176, 256, HG_SMEM>>>(xh, wqh, ctxh, wkvh);
    // flash attention split-KV -> g_po, g_pl
    attn_mma<<<dim3(8, 32, kSplits), 128, AT_SMEM>>>();
    // combine partials -> g_oh
    combine_kernel<<<2048, 256>>>();
    // out = g_oh @ Wout + bout
    out_gemm<<<dim3(32, 4), 256, HG_SMEM>>>(oh, wouth, bout, out);
}